// round 1
// baseline (speedup 1.0000x reference)
#include <cuda_runtime.h>
#include <cstddef>

// Problem constants
#define BATCH 2
#define SEQ   2048
#define DMODEL 1024
#define NHEADS 16
#define DHEAD 64
#define MROWS (BATCH*SEQ)        // 4096

// ---------------- scratch (no allocation allowed) ----------------
__device__ float g_q[BATCH*NHEADS*SEQ*DHEAD];   // [B,H,S,Dh]
__device__ float g_k[BATCH*NHEADS*SEQ*DHEAD];
__device__ float g_v[BATCH*NHEADS*SEQ*DHEAD];
__device__ float g_ao[MROWS*DMODEL];            // attention out, [B,S,D]

// ---------------- GEMM: Y = X @ W^T + b ----------------
// X: [M=4096, K=1024] row-major, W: [N=1024, K=1024] row-major.
// split==1: write to [B,H,S,Dh] layout; split==0: plain [M,N].
__global__ __launch_bounds__(256) void gemm_xwt(
    const float* __restrict__ X, const float* __restrict__ W,
    const float* __restrict__ bias, float* __restrict__ Y, int split)
{
    __shared__ float As[32][68];   // k-major, transposed tiles
    __shared__ float Bs[32][68];

    const int t  = threadIdx.x;            // 256 threads
    const int bm = blockIdx.y << 6;        // 64-row tile
    const int bn = blockIdx.x << 6;        // 64-col tile
    const int ty = t >> 4, tx = t & 15;

    float acc[4][4];
    #pragma unroll
    for (int i = 0; i < 4; i++)
        #pragma unroll
        for (int j = 0; j < 4; j++) acc[i][j] = 0.f;

    for (int k0 = 0; k0 < DMODEL; k0 += 32) {
        #pragma unroll
        for (int i = 0; i < 2; i++) {
            int id = (t << 1) + i;          // 0..511
            int r  = id >> 3;               // 0..63
            int kk = (id & 7) << 2;         // 0..28
            float4 a = *(const float4*)&X[(size_t)(bm + r) * DMODEL + k0 + kk];
            As[kk+0][r] = a.x; As[kk+1][r] = a.y; As[kk+2][r] = a.z; As[kk+3][r] = a.w;
            float4 w = *(const float4*)&W[(size_t)(bn + r) * DMODEL + k0 + kk];
            Bs[kk+0][r] = w.x; Bs[kk+1][r] = w.y; Bs[kk+2][r] = w.z; Bs[kk+3][r] = w.w;
        }
        __syncthreads();
        #pragma unroll
        for (int kk = 0; kk < 32; kk++) {
            float4 a4 = *(const float4*)&As[kk][ty << 2];
            float4 b4 = *(const float4*)&Bs[kk][tx << 2];
            float av[4] = {a4.x, a4.y, a4.z, a4.w};
            float bv[4] = {b4.x, b4.y, b4.z, b4.w};
            #pragma unroll
            for (int i = 0; i < 4; i++)
                #pragma unroll
                for (int j = 0; j < 4; j++)
                    acc[i][j] += av[i] * bv[j];
        }
        __syncthreads();
    }

    #pragma unroll
    for (int j = 0; j < 4; j++) {
        int n = bn + (tx << 2) + j;
        float bb = bias[n];
        #pragma unroll
        for (int i = 0; i < 4; i++) {
            int m = bm + (ty << 2) + i;
            float val = acc[i][j] + bb;
            if (!split) {
                Y[(size_t)m * DMODEL + n] = val;
            } else {
                int b_ = m >> 11;          // /SEQ
                int s  = m & (SEQ - 1);
                int h  = n >> 6;           // /DHEAD
                int dh = n & (DHEAD - 1);
                Y[(((size_t)(b_ * NHEADS + h)) * SEQ + s) * DHEAD + dh] = val;
            }
        }
    }
}

// ---------------- attention: streaming softmax(QK^T/8) V ----------------
// grid: (S/64, H, B), 256 threads. Q/K/V: [B,H,S,Dh]. Output: [B,S,D] concat heads.
#define TQPAD 68
__global__ __launch_bounds__(256) void attn_kernel(
    const float* __restrict__ Q, const float* __restrict__ K,
    const float* __restrict__ V, float* __restrict__ O)
{
    extern __shared__ float sm[];
    float (*Qs)[TQPAD] = (float (*)[TQPAD])sm;                        // [64][68] d-major
    float (*Ks)[TQPAD] = (float (*)[TQPAD])(sm + 64 * TQPAD);         // [64][68] d-major
    float (*Vs)[DHEAD] = (float (*)[DHEAD])(sm + 2 * 64 * TQPAD);     // [64][64] row-major
    float (*Ps)[TQPAD] = (float (*)[TQPAD])(sm + 2 * 64 * TQPAD + 64 * DHEAD); // [64][68]
    float* row_m  = sm + 3 * 64 * TQPAD + 64 * DHEAD;
    float* row_l  = row_m + 64;
    float* row_sc = row_l + 64;
    float* pm     = row_sc + 64;     // [64][4]
    float* psum   = pm + 256;        // [64][4]

    const int t  = threadIdx.x;
    const int b  = blockIdx.z, h = blockIdx.y;
    const int q0 = blockIdx.x << 6;
    const size_t head_base = ((size_t)(b * NHEADS + h)) * SEQ * DHEAD;

    // load Q tile (transposed: Qs[d][r])
    #pragma unroll
    for (int i = 0; i < 4; i++) {
        int id = t + 256 * i;
        int r  = id >> 4;
        int d4 = (id & 15) << 2;
        float4 v = *(const float4*)&Q[head_base + (size_t)(q0 + r) * DHEAD + d4];
        Qs[d4+0][r] = v.x; Qs[d4+1][r] = v.y; Qs[d4+2][r] = v.z; Qs[d4+3][r] = v.w;
    }
    if (t < 64) { row_m[t] = -1e30f; row_l[t] = 0.f; }

    float acc[16];
    #pragma unroll
    for (int i = 0; i < 16; i++) acc[i] = 0.f;

    const int ty = t >> 4, tx = t & 15;     // score tiling
    const int orow = t >> 2, oc0 = (t & 3) << 4;  // output tiling
    const int sg = t & 3;

    for (int kt = 0; kt < SEQ; kt += 64) {
        __syncthreads();   // protect Ks/Vs/Ps reuse; also orders Q load on iter 0
        #pragma unroll
        for (int i = 0; i < 4; i++) {
            int id = t + 256 * i;
            int r  = id >> 4;
            int d4 = (id & 15) << 2;
            float4 kv = *(const float4*)&K[head_base + (size_t)(kt + r) * DHEAD + d4];
            Ks[d4+0][r] = kv.x; Ks[d4+1][r] = kv.y; Ks[d4+2][r] = kv.z; Ks[d4+3][r] = kv.w;
            float4 vv = *(const float4*)&V[head_base + (size_t)(kt + r) * DHEAD + d4];
            *(float4*)&Vs[r][d4] = vv;
        }
        __syncthreads();

        // S = (Q K^T) * 1/8 into Ps
        float s4[4][4];
        #pragma unroll
        for (int i = 0; i < 4; i++)
            #pragma unroll
            for (int j = 0; j < 4; j++) s4[i][j] = 0.f;
        #pragma unroll 8
        for (int d = 0; d < DHEAD; d++) {
            float4 a4 = *(const float4*)&Qs[d][ty << 2];
            float4 b4 = *(const float4*)&Ks[d][tx << 2];
            float av[4] = {a4.x, a4.y, a4.z, a4.w};
            float bv[4] = {b4.x, b4.y, b4.z, b4.w};
            #pragma unroll
            for (int i = 0; i < 4; i++)
                #pragma unroll
                for (int j = 0; j < 4; j++)
                    s4[i][j] += av[i] * bv[j];
        }
        #pragma unroll
        for (int i = 0; i < 4; i++) {
            float4 out4 = make_float4(s4[i][0]*0.125f, s4[i][1]*0.125f,
                                      s4[i][2]*0.125f, s4[i][3]*0.125f);
            *(float4*)&Ps[(ty << 2) + i][tx << 2] = out4;
        }
        __syncthreads();

        // row max (partial, 4 segs per row)
        {
            float mx = -1e30f;
            #pragma unroll
            for (int c = 0; c < 16; c++) mx = fmaxf(mx, Ps[orow][(sg << 4) + c]);
            pm[orow * 4 + sg] = mx;
        }
        __syncthreads();
        if (t < 64) {
            float mx = fmaxf(fmaxf(pm[t*4], pm[t*4+1]), fmaxf(pm[t*4+2], pm[t*4+3]));
            float mold = row_m[t];
            float mnew = fmaxf(mold, mx);
            row_m[t]  = mnew;
            row_sc[t] = __expf(mold - mnew);
        }
        __syncthreads();
        // exp in place + partial sums
        {
            float mr = row_m[orow];
            float s = 0.f;
            #pragma unroll
            for (int c = 0; c < 16; c++) {
                float p = __expf(Ps[orow][(sg << 4) + c] - mr);
                Ps[orow][(sg << 4) + c] = p;
                s += p;
            }
            psum[orow * 4 + sg] = s;
        }
        __syncthreads();
        if (t < 64)
            row_l[t] = row_l[t] * row_sc[t]
                     + (psum[t*4] + psum[t*4+1] + psum[t*4+2] + psum[t*4+3]);

        // O update: acc = acc*scale + P V
        {
            float sc = row_sc[orow];
            #pragma unroll
            for (int i = 0; i < 16; i++) acc[i] *= sc;
            #pragma unroll 4
            for (int j = 0; j < 64; j++) {
                float p = Ps[orow][j];
                float4 v0 = *(const float4*)&Vs[j][oc0];
                float4 v1 = *(const float4*)&Vs[j][oc0 + 4];
                float4 v2 = *(const float4*)&Vs[j][oc0 + 8];
                float4 v3 = *(const float4*)&Vs[j][oc0 + 12];
                acc[0]  += p * v0.x; acc[1]  += p * v0.y; acc[2]  += p * v0.z; acc[3]  += p * v0.w;
                acc[4]  += p * v1.x; acc[5]  += p * v1.y; acc[6]  += p * v1.z; acc[7]  += p * v1.w;
                acc[8]  += p * v2.x; acc[9]  += p * v2.y; acc[10] += p * v2.z; acc[11] += p * v2.w;
                acc[12] += p * v3.x; acc[13] += p * v3.y; acc[14] += p * v3.z; acc[15] += p * v3.w;
            }
        }
    }
    __syncthreads();

    // epilogue: normalize, write [B,S,D] (concat heads)
    {
        float inv = 1.0f / row_l[orow];
        int s = q0 + orow;
        float* dst = &O[((size_t)(b * SEQ + s)) * DMODEL + h * DHEAD + oc0];
        #pragma unroll
        for (int c = 0; c < 16; c++) dst[c] = acc[c] * inv;
    }
}

// attn dynamic smem size
static const size_t ATTN_SMEM =
    (3 * 64 * TQPAD + 64 * DHEAD + 3 * 64 + 2 * 256) * sizeof(float);

extern "C" void kernel_launch(void* const* d_in, const int* in_sizes, int n_in,
                              void* d_out, int out_size)
{
    const float* query = (const float*)d_in[0];
    const float* key_  = (const float*)d_in[1];
    const float* value = (const float*)d_in[2];
    const float* Wq = (const float*)d_in[3];
    const float* bq = (const float*)d_in[4];
    const float* Wk = (const float*)d_in[5];
    const float* bk = (const float*)d_in[6];
    const float* Wv = (const float*)d_in[7];
    const float* bv = (const float*)d_in[8];
    const float* Wo = (const float*)d_in[9];
    const float* bo = (const float*)d_in[10];

    float *qptr, *kptr, *vptr, *aoptr;
    cudaGetSymbolAddress((void**)&qptr,  g_q);
    cudaGetSymbolAddress((void**)&kptr,  g_k);
    cudaGetSymbolAddress((void**)&vptr,  g_v);
    cudaGetSymbolAddress((void**)&aoptr, g_ao);

    cudaFuncSetAttribute(attn_kernel, cudaFuncAttributeMaxDynamicSharedMemorySize,
                         (int)ATTN_SMEM);

    dim3 ggrid(DMODEL / 64, MROWS / 64);   // (16, 64)
    gemm_xwt<<<ggrid, 256>>>(query, Wq, bq, qptr, 1);
    gemm_xwt<<<ggrid, 256>>>(key_,  Wk, bk, kptr, 1);
    gemm_xwt<<<ggrid, 256>>>(value, Wv, bv, vptr, 1);

    dim3 agrid(SEQ / 64, NHEADS, BATCH);   // (32, 16, 2)
    attn_kernel<<<agrid, 256, ATTN_SMEM>>>(qptr, kptr, vptr, aoptr);

    gemm_xwt<<<ggrid, 256>>>(aoptr, Wo, bo, (float*)d_out, 0);
}

// round 2
// speedup vs baseline: 3.5343x; 3.5343x over previous
#include <cuda_runtime.h>
#include <cstddef>

// Problem constants
#define BATCH 2
#define SEQ   2048
#define DMODEL 1024
#define NHEADS 16
#define DHEAD 64
#define MROWS (BATCH*SEQ)        // 4096

// ---------------- scratch (no allocation allowed) ----------------
__device__ float g_q[BATCH*NHEADS*SEQ*DHEAD];   // [B,H,S,Dh]
__device__ float g_k[BATCH*NHEADS*SEQ*DHEAD];
__device__ float g_v[BATCH*NHEADS*SEQ*DHEAD];
__device__ float g_ao[MROWS*DMODEL];            // attention out, [B,S,D]

// ---------------- tf32 helpers ----------------
__device__ __forceinline__ unsigned f2tf32(float x) {
    unsigned u;
    asm("cvt.rna.tf32.f32 %0, %1;" : "=r"(u) : "f"(x));
    return u;
}

__device__ __forceinline__ void mma_tf32(float* c, const unsigned* a, const unsigned* b) {
    asm volatile(
        "mma.sync.aligned.m16n8k8.row.col.f32.tf32.tf32.f32 "
        "{%0,%1,%2,%3}, {%4,%5,%6,%7}, {%8,%9}, {%0,%1,%2,%3};"
        : "+f"(c[0]), "+f"(c[1]), "+f"(c[2]), "+f"(c[3])
        : "r"(a[0]), "r"(a[1]), "r"(a[2]), "r"(a[3]),
          "r"(b[0]), "r"(b[1]));
}

// ---------------- GEMM (tf32 tensor): Y = X @ W^T + b ----------------
// X: [M=4096, K=1024] rm, W: [N=1024, K=1024] rm.
// split==1: write to [B,H,S,Dh]; split==0: plain [M,N].
#define GBM 128
#define GBN 128
#define GBK 32
#define GLD 133   // padded smem stride (conflict-free STS)

__global__ __launch_bounds__(256) void gemm_tf32(
    const float* __restrict__ X, const float* __restrict__ W,
    const float* __restrict__ bias, float* __restrict__ Y, int split)
{
    __shared__ float As[GBK][GLD];   // [k][m], tf32 bit patterns
    __shared__ float Bs[GBK][GLD];   // [k][n]

    const int t    = threadIdx.x;
    const int lane = t & 31;
    const int wid  = t >> 5;
    const int gid  = lane >> 2;      // 0..7
    const int tg   = lane & 3;       // 0..3

    const int bm = blockIdx.y * GBM;
    const int bn = blockIdx.x * GBN;
    const int m_base = (wid >> 1) * 32;   // warp rows (2 mtiles of 16)
    const int n_base = (wid & 1) * 64;    // warp cols (8 ntiles of 8)

    float acc[2][8][4];
    #pragma unroll
    for (int mt = 0; mt < 2; mt++)
        #pragma unroll
        for (int nt = 0; nt < 8; nt++)
            #pragma unroll
            for (int i = 0; i < 4; i++) acc[mt][nt][i] = 0.f;

    for (int k0 = 0; k0 < DMODEL; k0 += GBK) {
        // load + convert tiles
        #pragma unroll
        for (int l = 0; l < 4; l++) {
            int id = t + 256 * l;
            int r  = id >> 3;                 // 0..127
            int kc = (id & 7) << 2;           // 0..28
            float4 a = *(const float4*)&X[(size_t)(bm + r) * DMODEL + k0 + kc];
            As[kc+0][r] = __uint_as_float(f2tf32(a.x));
            As[kc+1][r] = __uint_as_float(f2tf32(a.y));
            As[kc+2][r] = __uint_as_float(f2tf32(a.z));
            As[kc+3][r] = __uint_as_float(f2tf32(a.w));
            float4 w = *(const float4*)&W[(size_t)(bn + r) * DMODEL + k0 + kc];
            Bs[kc+0][r] = __uint_as_float(f2tf32(w.x));
            Bs[kc+1][r] = __uint_as_float(f2tf32(w.y));
            Bs[kc+2][r] = __uint_as_float(f2tf32(w.z));
            Bs[kc+3][r] = __uint_as_float(f2tf32(w.w));
        }
        __syncthreads();

        #pragma unroll
        for (int ks = 0; ks < 4; ks++) {
            const int kb = ks * 8;
            unsigned afr[2][4];
            #pragma unroll
            for (int mt = 0; mt < 2; mt++) {
                int m = m_base + mt * 16;
                afr[mt][0] = __float_as_uint(As[kb + tg    ][m + gid    ]);
                afr[mt][1] = __float_as_uint(As[kb + tg    ][m + gid + 8]);
                afr[mt][2] = __float_as_uint(As[kb + 4 + tg][m + gid    ]);
                afr[mt][3] = __float_as_uint(As[kb + 4 + tg][m + gid + 8]);
            }
            unsigned bfr[8][2];
            #pragma unroll
            for (int nt = 0; nt < 8; nt++) {
                int n = n_base + nt * 8;
                bfr[nt][0] = __float_as_uint(Bs[kb + tg    ][n + gid]);
                bfr[nt][1] = __float_as_uint(Bs[kb + 4 + tg][n + gid]);
            }
            #pragma unroll
            for (int mt = 0; mt < 2; mt++)
                #pragma unroll
                for (int nt = 0; nt < 8; nt++)
                    mma_tf32(acc[mt][nt], afr[mt], bfr[nt]);
        }
        __syncthreads();
    }

    // epilogue
    #pragma unroll
    for (int nt = 0; nt < 8; nt++) {
        int c0 = bn + n_base + nt * 8 + tg * 2;
        float b0 = bias[c0], b1 = bias[c0 + 1];
        #pragma unroll
        for (int mt = 0; mt < 2; mt++) {
            int r0 = bm + m_base + mt * 16 + gid;
            #pragma unroll
            for (int half = 0; half < 2; half++) {
                int m = r0 + half * 8;
                float v0 = acc[mt][nt][half * 2 + 0] + b0;
                float v1 = acc[mt][nt][half * 2 + 1] + b1;
                if (!split) {
                    Y[(size_t)m * DMODEL + c0]     = v0;
                    Y[(size_t)m * DMODEL + c0 + 1] = v1;
                } else {
                    int b_ = m >> 11;
                    int s  = m & (SEQ - 1);
                    int h  = c0 >> 6;
                    int dh = c0 & (DHEAD - 1);
                    size_t base = (((size_t)(b_ * NHEADS + h)) * SEQ + s) * DHEAD;
                    Y[base + dh]     = v0;
                    Y[base + dh + 1] = v1;   // c0+1 same head (c0 even, dh<63)
                }
            }
        }
    }
}

// ---------------- attention: tensor-core flash-style ----------------
#define TQPAD 68
__global__ __launch_bounds__(256) void attn_kernel(
    const float* __restrict__ Q, const float* __restrict__ K,
    const float* __restrict__ V, float* __restrict__ O)
{
    extern __shared__ float sm[];
    float (*Qs)[TQPAD] = (float (*)[TQPAD])sm;                        // [d][r] tf32
    float (*Ks)[TQPAD] = (float (*)[TQPAD])(sm + 64 * TQPAD);        // [d][c] tf32
    float (*Vs)[TQPAD] = (float (*)[TQPAD])(sm + 2 * 64 * TQPAD);    // [k][d] tf32
    float (*Ps)[TQPAD] = (float (*)[TQPAD])(sm + 3 * 64 * TQPAD);    // fp32 scores/probs
    float* row_m  = sm + 4 * 64 * TQPAD;
    float* row_l  = row_m + 64;
    float* row_sc = row_l + 64;
    float* pm     = row_sc + 64;     // [64][4]
    float* psum   = pm + 256;        // [64][4]

    const int t    = threadIdx.x;
    const int lane = t & 31;
    const int wid  = t >> 5;
    const int gid  = lane >> 2;
    const int tg   = lane & 3;
    const int wm   = (wid >> 2) * 32;   // warp rows: 2 groups of 32
    const int wn   = (wid & 3) * 16;    // warp cols: 4 groups of 16

    const int b  = blockIdx.z, h = blockIdx.y;
    const int q0 = blockIdx.x << 6;
    const size_t head_base = ((size_t)(b * NHEADS + h)) * SEQ * DHEAD;

    // load Q tile scaled by 1/8, tf32, transposed: Qs[d][r]
    #pragma unroll
    for (int i = 0; i < 4; i++) {
        int id = t + 256 * i;
        int r  = id >> 4;
        int d4 = (id & 15) << 2;
        float4 v = *(const float4*)&Q[head_base + (size_t)(q0 + r) * DHEAD + d4];
        Qs[d4+0][r] = __uint_as_float(f2tf32(v.x * 0.125f));
        Qs[d4+1][r] = __uint_as_float(f2tf32(v.y * 0.125f));
        Qs[d4+2][r] = __uint_as_float(f2tf32(v.z * 0.125f));
        Qs[d4+3][r] = __uint_as_float(f2tf32(v.w * 0.125f));
    }
    if (t < 64) { row_m[t] = -1e30f; row_l[t] = 0.f; }

    float oacc[2][2][4];
    #pragma unroll
    for (int mt = 0; mt < 2; mt++)
        #pragma unroll
        for (int nt = 0; nt < 2; nt++)
            #pragma unroll
            for (int i = 0; i < 4; i++) oacc[mt][nt][i] = 0.f;

    const int orow = t >> 2, sg = t & 3;   // softmax worker layout

    for (int kt = 0; kt < SEQ; kt += 64) {
        __syncthreads();   // protect Ks/Vs/Ps reuse; orders Q load on iter 0
        #pragma unroll
        for (int i = 0; i < 4; i++) {
            int id = t + 256 * i;
            int r  = id >> 4;
            int d4 = (id & 15) << 2;
            float4 kv = *(const float4*)&K[head_base + (size_t)(kt + r) * DHEAD + d4];
            Ks[d4+0][r] = __uint_as_float(f2tf32(kv.x));
            Ks[d4+1][r] = __uint_as_float(f2tf32(kv.y));
            Ks[d4+2][r] = __uint_as_float(f2tf32(kv.z));
            Ks[d4+3][r] = __uint_as_float(f2tf32(kv.w));
            float4 vv = *(const float4*)&V[head_base + (size_t)(kt + r) * DHEAD + d4];
            Vs[r][d4+0] = __uint_as_float(f2tf32(vv.x));
            Vs[r][d4+1] = __uint_as_float(f2tf32(vv.y));
            Vs[r][d4+2] = __uint_as_float(f2tf32(vv.z));
            Vs[r][d4+3] = __uint_as_float(f2tf32(vv.w));
        }
        __syncthreads();

        // ---- scores: S = (Q/8) K^T via tf32 mma ----
        float sacc[2][2][4];
        #pragma unroll
        for (int mt = 0; mt < 2; mt++)
            #pragma unroll
            for (int nt = 0; nt < 2; nt++)
                #pragma unroll
                for (int i = 0; i < 4; i++) sacc[mt][nt][i] = 0.f;

        #pragma unroll
        for (int ks = 0; ks < 8; ks++) {
            const int kb = ks * 8;
            unsigned afr[2][4];
            #pragma unroll
            for (int mt = 0; mt < 2; mt++) {
                int m = wm + mt * 16;
                afr[mt][0] = __float_as_uint(Qs[kb + tg    ][m + gid    ]);
                afr[mt][1] = __float_as_uint(Qs[kb + tg    ][m + gid + 8]);
                afr[mt][2] = __float_as_uint(Qs[kb + 4 + tg][m + gid    ]);
                afr[mt][3] = __float_as_uint(Qs[kb + 4 + tg][m + gid + 8]);
            }
            unsigned bfr[2][2];
            #pragma unroll
            for (int nt = 0; nt < 2; nt++) {
                int n = wn + nt * 8;
                bfr[nt][0] = __float_as_uint(Ks[kb + tg    ][n + gid]);
                bfr[nt][1] = __float_as_uint(Ks[kb + 4 + tg][n + gid]);
            }
            #pragma unroll
            for (int mt = 0; mt < 2; mt++)
                #pragma unroll
                for (int nt = 0; nt < 2; nt++)
                    mma_tf32(sacc[mt][nt], afr[mt], bfr[nt]);
        }
        // scatter scores to smem
        #pragma unroll
        for (int mt = 0; mt < 2; mt++) {
            int r = wm + mt * 16 + gid;
            #pragma unroll
            for (int nt = 0; nt < 2; nt++) {
                int c = wn + nt * 8 + tg * 2;
                Ps[r    ][c]     = sacc[mt][nt][0];
                Ps[r    ][c + 1] = sacc[mt][nt][1];
                Ps[r + 8][c]     = sacc[mt][nt][2];
                Ps[r + 8][c + 1] = sacc[mt][nt][3];
            }
        }
        __syncthreads();

        // ---- online softmax (fp32 in smem) ----
        {
            float mx = -1e30f;
            #pragma unroll
            for (int c = 0; c < 16; c++) mx = fmaxf(mx, Ps[orow][(sg << 4) + c]);
            pm[orow * 4 + sg] = mx;
        }
        __syncthreads();
        if (t < 64) {
            float mx = fmaxf(fmaxf(pm[t*4], pm[t*4+1]), fmaxf(pm[t*4+2], pm[t*4+3]));
            float mold = row_m[t];
            float mnew = fmaxf(mold, mx);
            row_m[t]  = mnew;
            row_sc[t] = __expf(mold - mnew);
        }
        __syncthreads();
        {
            float mr = row_m[orow];
            float s = 0.f;
            #pragma unroll
            for (int c = 0; c < 16; c++) {
                float p = __expf(Ps[orow][(sg << 4) + c] - mr);
                Ps[orow][(sg << 4) + c] = p;
                s += p;
            }
            psum[orow * 4 + sg] = s;
        }
        __syncthreads();
        if (t < 64)
            row_l[t] = row_l[t] * row_sc[t]
                     + (psum[t*4] + psum[t*4+1] + psum[t*4+2] + psum[t*4+3]);

        // ---- PV: oacc = oacc*sc + P @ V via tf32 mma ----
        {
            float sc_lo = row_sc[wm + gid];           // rows gid (+mt*16)
            // per-mtile row scales
            #pragma unroll
            for (int mt = 0; mt < 2; mt++) {
                float s0 = row_sc[wm + mt * 16 + gid];
                float s1 = row_sc[wm + mt * 16 + gid + 8];
                #pragma unroll
                for (int nt = 0; nt < 2; nt++) {
                    oacc[mt][nt][0] *= s0; oacc[mt][nt][1] *= s0;
                    oacc[mt][nt][2] *= s1; oacc[mt][nt][3] *= s1;
                }
            }
            (void)sc_lo;
            #pragma unroll
            for (int ks = 0; ks < 8; ks++) {
                const int kb = ks * 8;
                unsigned afr[2][4];
                #pragma unroll
                for (int mt = 0; mt < 2; mt++) {
                    int m = wm + mt * 16;
                    afr[mt][0] = f2tf32(Ps[m + gid    ][kb + tg    ]);
                    afr[mt][1] = f2tf32(Ps[m + gid + 8][kb + tg    ]);
                    afr[mt][2] = f2tf32(Ps[m + gid    ][kb + 4 + tg]);
                    afr[mt][3] = f2tf32(Ps[m + gid + 8][kb + 4 + tg]);
                }
                unsigned bfr[2][2];
                #pragma unroll
                for (int nt = 0; nt < 2; nt++) {
                    int n = wn + nt * 8;
                    bfr[nt][0] = __float_as_uint(Vs[kb + tg    ][n + gid]);
                    bfr[nt][1] = __float_as_uint(Vs[kb + 4 + tg][n + gid]);
                }
                #pragma unroll
                for (int mt = 0; mt < 2; mt++)
                    #pragma unroll
                    for (int nt = 0; nt < 2; nt++)
                        mma_tf32(oacc[mt][nt], afr[mt], bfr[nt]);
            }
        }
    }
    __syncthreads();

    // epilogue: normalize, write [B,S,D] (concat heads)
    #pragma unroll
    for (int mt = 0; mt < 2; mt++) {
        int r0 = wm + mt * 16 + gid;
        float inv0 = 1.0f / row_l[r0];
        float inv1 = 1.0f / row_l[r0 + 8];
        #pragma unroll
        for (int nt = 0; nt < 2; nt++) {
            int c = wn + nt * 8 + tg * 2;
            size_t base0 = ((size_t)(b * SEQ + q0 + r0)) * DMODEL + h * DHEAD + c;
            size_t base1 = ((size_t)(b * SEQ + q0 + r0 + 8)) * DMODEL + h * DHEAD + c;
            O[base0]     = oacc[mt][nt][0] * inv0;
            O[base0 + 1] = oacc[mt][nt][1] * inv0;
            O[base1]     = oacc[mt][nt][2] * inv1;
            O[base1 + 1] = oacc[mt][nt][3] * inv1;
        }
    }
}

// attn dynamic smem size
static const size_t ATTN_SMEM =
    (4 * 64 * TQPAD + 3 * 64 + 2 * 256) * sizeof(float);

extern "C" void kernel_launch(void* const* d_in, const int* in_sizes, int n_in,
                              void* d_out, int out_size)
{
    const float* query = (const float*)d_in[0];
    const float* key_  = (const float*)d_in[1];
    const float* value = (const float*)d_in[2];
    const float* Wq = (const float*)d_in[3];
    const float* bq = (const float*)d_in[4];
    const float* Wk = (const float*)d_in[5];
    const float* bk = (const float*)d_in[6];
    const float* Wv = (const float*)d_in[7];
    const float* bv = (const float*)d_in[8];
    const float* Wo = (const float*)d_in[9];
    const float* bo = (const float*)d_in[10];

    float *qptr, *kptr, *vptr, *aoptr;
    cudaGetSymbolAddress((void**)&qptr,  g_q);
    cudaGetSymbolAddress((void**)&kptr,  g_k);
    cudaGetSymbolAddress((void**)&vptr,  g_v);
    cudaGetSymbolAddress((void**)&aoptr, g_ao);

    cudaFuncSetAttribute(attn_kernel, cudaFuncAttributeMaxDynamicSharedMemorySize,
                         (int)ATTN_SMEM);

    dim3 ggrid(DMODEL / GBN, MROWS / GBM);   // (8, 32)
    gemm_tf32<<<ggrid, 256>>>(query, Wq, bq, qptr, 1);
    gemm_tf32<<<ggrid, 256>>>(key_,  Wk, bk, kptr, 1);
    gemm_tf32<<<ggrid, 256>>>(value, Wv, bv, vptr, 1);

    dim3 agrid(SEQ / 64, NHEADS, BATCH);   // (32, 16, 2)
    attn_kernel<<<agrid, 256, ATTN_SMEM>>>(qptr, kptr, vptr, aoptr);

    gemm_tf32<<<ggrid, 256>>>(aoptr, Wo, bo, (float*)d_out, 0);
}

// round 3
// speedup vs baseline: 4.9232x; 1.3930x over previous
#include <cuda_runtime.h>
#include <cstddef>

// Problem constants
#define BATCH 2
#define SEQ   2048
#define DMODEL 1024
#define NHEADS 16
#define DHEAD 64
#define MROWS (BATCH*SEQ)        // 4096

// ---------------- scratch (no allocation allowed) ----------------
__device__ float g_q[BATCH*NHEADS*SEQ*DHEAD];   // [B,H,S,Dh]
__device__ float g_k[BATCH*NHEADS*SEQ*DHEAD];
__device__ float g_v[BATCH*NHEADS*SEQ*DHEAD];
__device__ float g_ao[MROWS*DMODEL];            // attention out, [B,S,D]

// ---------------- tf32 helpers ----------------
__device__ __forceinline__ unsigned f2tf32(float x) {
    unsigned u;
    asm("cvt.rna.tf32.f32 %0, %1;" : "=r"(u) : "f"(x));
    return u;
}

__device__ __forceinline__ void mma_tf32(float* c, const unsigned* a, const unsigned* b) {
    asm volatile(
        "mma.sync.aligned.m16n8k8.row.col.f32.tf32.tf32.f32 "
        "{%0,%1,%2,%3}, {%4,%5,%6,%7}, {%8,%9}, {%0,%1,%2,%3};"
        : "+f"(c[0]), "+f"(c[1]), "+f"(c[2]), "+f"(c[3])
        : "r"(a[0]), "r"(a[1]), "r"(a[2]), "r"(a[3]),
          "r"(b[0]), "r"(b[1]));
}

// ---------------- GEMM (tf32 tensor): Y = X @ W^T + b ----------------
#define GBM 128
#define GBN 128
#define GBK 32
#define GLD 133

__global__ __launch_bounds__(256) void gemm_tf32(
    const float* __restrict__ X, const float* __restrict__ W,
    const float* __restrict__ bias, float* __restrict__ Y, int split)
{
    __shared__ float As[GBK][GLD];
    __shared__ float Bs[GBK][GLD];

    const int t    = threadIdx.x;
    const int lane = t & 31;
    const int wid  = t >> 5;
    const int gid  = lane >> 2;
    const int tg   = lane & 3;

    const int bm = blockIdx.y * GBM;
    const int bn = blockIdx.x * GBN;
    const int m_base = (wid >> 1) * 32;
    const int n_base = (wid & 1) * 64;

    float acc[2][8][4];
    #pragma unroll
    for (int mt = 0; mt < 2; mt++)
        #pragma unroll
        for (int nt = 0; nt < 8; nt++)
            #pragma unroll
            for (int i = 0; i < 4; i++) acc[mt][nt][i] = 0.f;

    for (int k0 = 0; k0 < DMODEL; k0 += GBK) {
        #pragma unroll
        for (int l = 0; l < 4; l++) {
            int id = t + 256 * l;
            int r  = id >> 3;
            int kc = (id & 7) << 2;
            float4 a = *(const float4*)&X[(size_t)(bm + r) * DMODEL + k0 + kc];
            As[kc+0][r] = __uint_as_float(f2tf32(a.x));
            As[kc+1][r] = __uint_as_float(f2tf32(a.y));
            As[kc+2][r] = __uint_as_float(f2tf32(a.z));
            As[kc+3][r] = __uint_as_float(f2tf32(a.w));
            float4 w = *(const float4*)&W[(size_t)(bn + r) * DMODEL + k0 + kc];
            Bs[kc+0][r] = __uint_as_float(f2tf32(w.x));
            Bs[kc+1][r] = __uint_as_float(f2tf32(w.y));
            Bs[kc+2][r] = __uint_as_float(f2tf32(w.z));
            Bs[kc+3][r] = __uint_as_float(f2tf32(w.w));
        }
        __syncthreads();

        #pragma unroll
        for (int ks = 0; ks < 4; ks++) {
            const int kb = ks * 8;
            unsigned afr[2][4];
            #pragma unroll
            for (int mt = 0; mt < 2; mt++) {
                int m = m_base + mt * 16;
                afr[mt][0] = __float_as_uint(As[kb + tg    ][m + gid    ]);
                afr[mt][1] = __float_as_uint(As[kb + tg    ][m + gid + 8]);
                afr[mt][2] = __float_as_uint(As[kb + 4 + tg][m + gid    ]);
                afr[mt][3] = __float_as_uint(As[kb + 4 + tg][m + gid + 8]);
            }
            unsigned bfr[8][2];
            #pragma unroll
            for (int nt = 0; nt < 8; nt++) {
                int n = n_base + nt * 8;
                bfr[nt][0] = __float_as_uint(Bs[kb + tg    ][n + gid]);
                bfr[nt][1] = __float_as_uint(Bs[kb + 4 + tg][n + gid]);
            }
            #pragma unroll
            for (int mt = 0; mt < 2; mt++)
                #pragma unroll
                for (int nt = 0; nt < 8; nt++)
                    mma_tf32(acc[mt][nt], afr[mt], bfr[nt]);
        }
        __syncthreads();
    }

    #pragma unroll
    for (int nt = 0; nt < 8; nt++) {
        int c0 = bn + n_base + nt * 8 + tg * 2;
        float b0 = bias[c0], b1 = bias[c0 + 1];
        #pragma unroll
        for (int mt = 0; mt < 2; mt++) {
            int r0 = bm + m_base + mt * 16 + gid;
            #pragma unroll
            for (int half = 0; half < 2; half++) {
                int m = r0 + half * 8;
                float v0 = acc[mt][nt][half * 2 + 0] + b0;
                float v1 = acc[mt][nt][half * 2 + 1] + b1;
                if (!split) {
                    Y[(size_t)m * DMODEL + c0]     = v0;
                    Y[(size_t)m * DMODEL + c0 + 1] = v1;
                } else {
                    int b_ = m >> 11;
                    int s  = m & (SEQ - 1);
                    int h  = c0 >> 6;
                    int dh = c0 & (DHEAD - 1);
                    size_t base = (((size_t)(b_ * NHEADS + h)) * SEQ + s) * DHEAD;
                    Y[base + dh]     = v0;
                    Y[base + dh + 1] = v1;
                }
            }
        }
    }
}

// ---------------- attention: register-resident flash (tf32 mma) ----------------
// 256 threads = 8 warps; each warp owns 16 q-rows x all 64 key cols.
// Br=128 rows/CTA. grid = (SEQ/128, H, B).
#define APAD 68   // K & Q staging row pad (floats)
#define VPAD 72   // V row pad (floats) -> conflict-free b-frag loads

__global__ __launch_bounds__(256) void attn_kernel(
    const float* __restrict__ Q, const float* __restrict__ K,
    const float* __restrict__ V, float* __restrict__ O)
{
    extern __shared__ float sm[];
    float (*Ks)[APAD] = (float (*)[APAD])sm;                 // [64][68]
    float (*Vs)[VPAD] = (float (*)[VPAD])(sm + 64 * APAD);   // [64][72]
    float (*Qs)[APAD] = (float (*)[APAD])sm;                 // alias: Q staging pre-loop [128][68]

    const int t    = threadIdx.x;
    const int lane = t & 31;
    const int wid  = t >> 5;
    const int gid  = lane >> 2;
    const int tg   = lane & 3;

    const int b  = blockIdx.z, h = blockIdx.y;
    const int q0 = blockIdx.x << 7;                 // 128 rows per CTA
    const size_t head_base = ((size_t)(b * NHEADS + h)) * SEQ * DHEAD;

    // ---- stage Q (scaled by 1/8, tf32) into smem, then extract a-frags to regs ----
    #pragma unroll
    for (int l = 0; l < 8; l++) {
        int id = t + 256 * l;
        int r  = id >> 4;
        int d4 = (id & 15) << 2;
        float4 v = *(const float4*)&Q[head_base + (size_t)(q0 + r) * DHEAD + d4];
        Qs[r][d4+0] = __uint_as_float(f2tf32(v.x * 0.125f));
        Qs[r][d4+1] = __uint_as_float(f2tf32(v.y * 0.125f));
        Qs[r][d4+2] = __uint_as_float(f2tf32(v.z * 0.125f));
        Qs[r][d4+3] = __uint_as_float(f2tf32(v.w * 0.125f));
    }
    __syncthreads();

    unsigned qf[8][4];
    {
        const int wrow = wid * 16;
        #pragma unroll
        for (int ks = 0; ks < 8; ks++) {
            const int kb = ks * 8;
            qf[ks][0] = __float_as_uint(Qs[wrow + gid    ][kb + tg    ]);
            qf[ks][1] = __float_as_uint(Qs[wrow + gid + 8][kb + tg    ]);
            qf[ks][2] = __float_as_uint(Qs[wrow + gid    ][kb + 4 + tg]);
            qf[ks][3] = __float_as_uint(Qs[wrow + gid + 8][kb + 4 + tg]);
        }
    }

    float oacc[8][4];
    #pragma unroll
    for (int nt = 0; nt < 8; nt++)
        #pragma unroll
        for (int i = 0; i < 4; i++) oacc[nt][i] = 0.f;
    float m0 = -1e30f, m1 = -1e30f, l0 = 0.f, l1 = 0.f;

    const int src1 = (lane & ~3) | (tg >> 1);
    const int src2 = src1 + 2;
    const bool odd = (tg & 1);

    for (int kt = 0; kt < SEQ; kt += 64) {
        __syncthreads();   // protect Ks/Vs reuse (and Q staging on iter 0)
        #pragma unroll
        for (int l = 0; l < 4; l++) {
            int id = t + 256 * l;
            int r  = id >> 4;
            int d4 = (id & 15) << 2;
            float4 kv = *(const float4*)&K[head_base + (size_t)(kt + r) * DHEAD + d4];
            Ks[r][d4+0] = __uint_as_float(f2tf32(kv.x));
            Ks[r][d4+1] = __uint_as_float(f2tf32(kv.y));
            Ks[r][d4+2] = __uint_as_float(f2tf32(kv.z));
            Ks[r][d4+3] = __uint_as_float(f2tf32(kv.w));
            float4 vv = *(const float4*)&V[head_base + (size_t)(kt + r) * DHEAD + d4];
            Vs[r][d4+0] = __uint_as_float(f2tf32(vv.x));
            Vs[r][d4+1] = __uint_as_float(f2tf32(vv.y));
            Vs[r][d4+2] = __uint_as_float(f2tf32(vv.z));
            Vs[r][d4+3] = __uint_as_float(f2tf32(vv.w));
        }
        __syncthreads();

        // ---- S = (Q/8) K^T : 16 rows x 64 cols per warp, all in regs ----
        float sacc[8][4];
        #pragma unroll
        for (int nt = 0; nt < 8; nt++)
            #pragma unroll
            for (int i = 0; i < 4; i++) sacc[nt][i] = 0.f;

        #pragma unroll
        for (int ks = 0; ks < 8; ks++) {
            const int kb = ks * 8;
            unsigned bfr[8][2];
            #pragma unroll
            for (int nt = 0; nt < 8; nt++) {
                bfr[nt][0] = __float_as_uint(Ks[nt * 8 + gid][kb + tg    ]);
                bfr[nt][1] = __float_as_uint(Ks[nt * 8 + gid][kb + 4 + tg]);
            }
            #pragma unroll
            for (int nt = 0; nt < 8; nt++)
                mma_tf32(sacc[nt], qf[ks], bfr[nt]);
        }

        // ---- online softmax, all register/shuffle ----
        float mx0 = -1e30f, mx1 = -1e30f;
        #pragma unroll
        for (int nt = 0; nt < 8; nt++) {
            mx0 = fmaxf(mx0, fmaxf(sacc[nt][0], sacc[nt][1]));
            mx1 = fmaxf(mx1, fmaxf(sacc[nt][2], sacc[nt][3]));
        }
        mx0 = fmaxf(mx0, __shfl_xor_sync(0xffffffffu, mx0, 1));
        mx0 = fmaxf(mx0, __shfl_xor_sync(0xffffffffu, mx0, 2));
        mx1 = fmaxf(mx1, __shfl_xor_sync(0xffffffffu, mx1, 1));
        mx1 = fmaxf(mx1, __shfl_xor_sync(0xffffffffu, mx1, 2));

        float m0n = fmaxf(m0, mx0), m1n = fmaxf(m1, mx1);
        float sc0 = __expf(m0 - m0n), sc1 = __expf(m1 - m1n);
        m0 = m0n; m1 = m1n;

        float s0 = 0.f, s1 = 0.f;
        #pragma unroll
        for (int nt = 0; nt < 8; nt++) {
            sacc[nt][0] = __expf(sacc[nt][0] - m0); s0 += sacc[nt][0];
            sacc[nt][1] = __expf(sacc[nt][1] - m0); s0 += sacc[nt][1];
            sacc[nt][2] = __expf(sacc[nt][2] - m1); s1 += sacc[nt][2];
            sacc[nt][3] = __expf(sacc[nt][3] - m1); s1 += sacc[nt][3];
        }
        s0 += __shfl_xor_sync(0xffffffffu, s0, 1);
        s0 += __shfl_xor_sync(0xffffffffu, s0, 2);
        s1 += __shfl_xor_sync(0xffffffffu, s1, 1);
        s1 += __shfl_xor_sync(0xffffffffu, s1, 2);
        l0 = l0 * sc0 + s0;
        l1 = l1 * sc1 + s1;

        #pragma unroll
        for (int nt = 0; nt < 8; nt++) {
            oacc[nt][0] *= sc0; oacc[nt][1] *= sc0;
            oacc[nt][2] *= sc1; oacc[nt][3] *= sc1;
        }

        // ---- PV: P c-frag -> a-frag via quad shuffles, then mma with V ----
        #pragma unroll
        for (int ks = 0; ks < 8; ks++) {
            float p0 = sacc[ks][0], p1 = sacc[ks][1];
            float p2 = sacc[ks][2], p3 = sacc[ks][3];
            float v00 = __shfl_sync(0xffffffffu, p0, src1);
            float v01 = __shfl_sync(0xffffffffu, p1, src1);
            float v10 = __shfl_sync(0xffffffffu, p2, src1);
            float v11 = __shfl_sync(0xffffffffu, p3, src1);
            float v20 = __shfl_sync(0xffffffffu, p0, src2);
            float v21 = __shfl_sync(0xffffffffu, p1, src2);
            float v30 = __shfl_sync(0xffffffffu, p2, src2);
            float v31 = __shfl_sync(0xffffffffu, p3, src2);
            unsigned a[4];
            a[0] = f2tf32(odd ? v01 : v00);
            a[1] = f2tf32(odd ? v11 : v10);
            a[2] = f2tf32(odd ? v21 : v20);
            a[3] = f2tf32(odd ? v31 : v30);

            const int kb = ks * 8;
            #pragma unroll
            for (int nt = 0; nt < 8; nt++) {
                unsigned b2[2];
                b2[0] = __float_as_uint(Vs[kb + tg    ][nt * 8 + gid]);
                b2[1] = __float_as_uint(Vs[kb + 4 + tg][nt * 8 + gid]);
                mma_tf32(oacc[nt], a, b2);
            }
        }
    }

    // ---- epilogue: normalize, write [B,S,D] (concat heads) ----
    {
        float il0 = 1.0f / l0, il1 = 1.0f / l1;
        int r0 = q0 + wid * 16 + gid;
        int r1 = r0 + 8;
        #pragma unroll
        for (int nt = 0; nt < 8; nt++) {
            int c = h * DHEAD + nt * 8 + tg * 2;
            float2 o0 = make_float2(oacc[nt][0] * il0, oacc[nt][1] * il0);
            float2 o1 = make_float2(oacc[nt][2] * il1, oacc[nt][3] * il1);
            *(float2*)&O[((size_t)(b * SEQ + r0)) * DMODEL + c] = o0;
            *(float2*)&O[((size_t)(b * SEQ + r1)) * DMODEL + c] = o1;
        }
    }
}

// attn dynamic smem: max(Q staging 128*68, K 64*68 + V 64*72) floats
static const size_t ATTN_SMEM =
    ((64 * APAD + 64 * VPAD) > (128 * APAD) ? (64 * APAD + 64 * VPAD)
                                            : (128 * APAD)) * sizeof(float);

extern "C" void kernel_launch(void* const* d_in, const int* in_sizes, int n_in,
                              void* d_out, int out_size)
{
    const float* query = (const float*)d_in[0];
    const float* key_  = (const float*)d_in[1];
    const float* value = (const float*)d_in[2];
    const float* Wq = (const float*)d_in[3];
    const float* bq = (const float*)d_in[4];
    const float* Wk = (const float*)d_in[5];
    const float* bk = (const float*)d_in[6];
    const float* Wv = (const float*)d_in[7];
    const float* bv = (const float*)d_in[8];
    const float* Wo = (const float*)d_in[9];
    const float* bo = (const float*)d_in[10];

    float *qptr, *kptr, *vptr, *aoptr;
    cudaGetSymbolAddress((void**)&qptr,  g_q);
    cudaGetSymbolAddress((void**)&kptr,  g_k);
    cudaGetSymbolAddress((void**)&vptr,  g_v);
    cudaGetSymbolAddress((void**)&aoptr, g_ao);

    cudaFuncSetAttribute(attn_kernel, cudaFuncAttributeMaxDynamicSharedMemorySize,
                         (int)ATTN_SMEM);

    dim3 ggrid(DMODEL / GBN, MROWS / GBM);   // (8, 32)
    gemm_tf32<<<ggrid, 256>>>(query, Wq, bq, qptr, 1);
    gemm_tf32<<<ggrid, 256>>>(key_,  Wk, bk, kptr, 1);
    gemm_tf32<<<ggrid, 256>>>(value, Wv, bv, vptr, 1);

    dim3 agrid(SEQ / 128, NHEADS, BATCH);    // (16, 16, 2)
    attn_kernel<<<agrid, 256, ATTN_SMEM>>>(qptr, kptr, vptr, aoptr);

    gemm_tf32<<<ggrid, 256>>>(aoptr, Wo, bo, (float*)d_out, 0);
}

// round 5
// speedup vs baseline: 5.9977x; 1.2183x over previous
#include <cuda_runtime.h>
#include <cstddef>
#include <cstdint>

// Problem constants
#define BATCH 2
#define SEQ   2048
#define DMODEL 1024
#define NHEADS 16
#define DHEAD 64
#define MROWS (BATCH*SEQ)        // 4096

// ---------------- scratch (no allocation allowed) ----------------
__device__ float g_q[BATCH*NHEADS*SEQ*DHEAD];   // [B,H,S,Dh]
__device__ float g_k[BATCH*NHEADS*SEQ*DHEAD];
__device__ float g_v[BATCH*NHEADS*SEQ*DHEAD];
__device__ float g_ao[MROWS*DMODEL];            // attention out, [B,S,D]

// ---------------- helpers ----------------
__device__ __forceinline__ unsigned f2tf32(float x) {
    unsigned u;
    asm("cvt.rna.tf32.f32 %0, %1;" : "=r"(u) : "f"(x));
    return u;
}

__device__ __forceinline__ float cvt_tf32f(float x) {
    unsigned u;
    asm("cvt.rna.tf32.f32 %0, %1;" : "=r"(u) : "f"(x));
    return __uint_as_float(u);
}

__device__ __forceinline__ void mma_tf32(float* c, const unsigned* a, const unsigned* b) {
    asm volatile(
        "mma.sync.aligned.m16n8k8.row.col.f32.tf32.tf32.f32 "
        "{%0,%1,%2,%3}, {%4,%5,%6,%7}, {%8,%9}, {%0,%1,%2,%3};"
        : "+f"(c[0]), "+f"(c[1]), "+f"(c[2]), "+f"(c[3])
        : "r"(a[0]), "r"(a[1]), "r"(a[2]), "r"(a[3]),
          "r"(b[0]), "r"(b[1]));
}

__device__ __forceinline__ uint32_t smem_u32(const void* p) {
    uint32_t a;
    asm("{ .reg .u64 t; cvta.to.shared.u64 t, %1; cvt.u32.u64 %0, t; }"
        : "=r"(a) : "l"(p));
    return a;
}

__device__ __forceinline__ void cpa16(uint32_t dst, const void* src) {
    asm volatile("cp.async.cg.shared.global [%0], [%1], 16;"
                 :: "r"(dst), "l"(src) : "memory");
}
#define CPA_COMMIT() asm volatile("cp.async.commit_group;" ::: "memory")
#define CPA_WAIT1()  asm volatile("cp.async.wait_group 1;" ::: "memory")
#define CPA_WAIT0()  asm volatile("cp.async.wait_group 0;" ::: "memory")

// ---------------- GEMM (tf32 mma + cp.async pipeline): Y = X @ W^T + b ----
// Tile 128x128x32, 256 threads (8 warps: 4m x 2n), double-buffered smem.
// Smem float offsets: As[2] pitch 36, Bs[2] pitch 36.
#define GP 36
#define G_AS0 0
#define G_AS1 4608
#define G_BS0 9216
#define G_BS1 13824
#define G_SMEM_FLOATS 18432   // 73728 bytes

__global__ __launch_bounds__(256) void gemm_tf32(
    const float* __restrict__ X, const float* __restrict__ W,
    const float* __restrict__ bias, float* __restrict__ Y, int split)
{
    extern __shared__ float sg[];
    const uint32_t smb = smem_u32(sg);

    const int t    = threadIdx.x;
    const int lane = t & 31;
    const int wid  = t >> 5;
    const int gid  = lane >> 2;
    const int tg   = lane & 3;

    const int bm = blockIdx.y * 128;
    const int bn = blockIdx.x * 128;
    const int m_base = (wid >> 1) * 32;
    const int n_base = (wid & 1) * 64;

    // per-thread copy coords: 4 chunks for A, 4 for B
    const int cr = t >> 1;            // 0..127 (two threads per row)
    const int cq = (t & 1) * 4;       // chunk col pair base (q in {0,4})

    float acc[2][8][4];
    #pragma unroll
    for (int mt = 0; mt < 2; mt++)
        #pragma unroll
        for (int nt = 0; nt < 8; nt++)
            #pragma unroll
            for (int i = 0; i < 4; i++) acc[mt][nt][i] = 0.f;

    // prefetch chunk 0 into buffer 0
    {
        const float* xs = X + (size_t)bm * DMODEL;
        const float* ws = W + (size_t)bn * DMODEL;
        #pragma unroll
        for (int l = 0; l < 4; l++) {
            int id = t + 256 * l;
            int r  = id >> 3, q = id & 7;
            cpa16(smb + (uint32_t)(G_AS0 + r * GP + q * 4) * 4,
                  xs + (size_t)r * DMODEL + q * 4);
            cpa16(smb + (uint32_t)(G_BS0 + r * GP + q * 4) * 4,
                  ws + (size_t)r * DMODEL + q * 4);
        }
        CPA_COMMIT();
    }
    (void)cr; (void)cq;

    for (int c = 0; c < 32; c++) {
        const int buf  = c & 1;
        const int aoff = buf ? G_AS1 : G_AS0;
        const int boff = buf ? G_BS1 : G_BS0;

        if (c + 1 < 32) {
            const int nb   = (c + 1) & 1;
            const int naof = nb ? G_AS1 : G_AS0;
            const int nbof = nb ? G_BS1 : G_BS0;
            const int k0   = (c + 1) * 32;
            const float* xs = X + (size_t)bm * DMODEL + k0;
            const float* ws = W + (size_t)bn * DMODEL + k0;
            #pragma unroll
            for (int l = 0; l < 4; l++) {
                int id = t + 256 * l;
                int r  = id >> 3, q = id & 7;
                cpa16(smb + (uint32_t)(naof + r * GP + q * 4) * 4,
                      xs + (size_t)r * DMODEL + q * 4);
                cpa16(smb + (uint32_t)(nbof + r * GP + q * 4) * 4,
                      ws + (size_t)r * DMODEL + q * 4);
            }
            CPA_COMMIT();
            CPA_WAIT1();
        } else {
            CPA_WAIT0();
        }
        __syncthreads();

        const float* As = sg + aoff;
        const float* Bs = sg + boff;
        #pragma unroll
        for (int ks = 0; ks < 4; ks++) {
            const int kb = ks * 8;
            unsigned afr[2][4];
            #pragma unroll
            for (int mt = 0; mt < 2; mt++) {
                int m = m_base + mt * 16;
                afr[mt][0] = f2tf32(As[(m + gid    ) * GP + kb + tg    ]);
                afr[mt][1] = f2tf32(As[(m + gid + 8) * GP + kb + tg    ]);
                afr[mt][2] = f2tf32(As[(m + gid    ) * GP + kb + 4 + tg]);
                afr[mt][3] = f2tf32(As[(m + gid + 8) * GP + kb + 4 + tg]);
            }
            unsigned bfr[8][2];
            #pragma unroll
            for (int nt = 0; nt < 8; nt++) {
                int n = n_base + nt * 8;
                bfr[nt][0] = f2tf32(Bs[(n + gid) * GP + kb + tg    ]);
                bfr[nt][1] = f2tf32(Bs[(n + gid) * GP + kb + 4 + tg]);
            }
            #pragma unroll
            for (int mt = 0; mt < 2; mt++)
                #pragma unroll
                for (int nt = 0; nt < 8; nt++)
                    mma_tf32(acc[mt][nt], afr[mt], bfr[nt]);
        }
        __syncthreads();   // before next iter's prefetch overwrites this buf
    }

    // epilogue
    #pragma unroll
    for (int nt = 0; nt < 8; nt++) {
        int c0 = bn + n_base + nt * 8 + tg * 2;
        float b0 = bias[c0], b1 = bias[c0 + 1];
        #pragma unroll
        for (int mt = 0; mt < 2; mt++) {
            int r0 = bm + m_base + mt * 16 + gid;
            #pragma unroll
            for (int half = 0; half < 2; half++) {
                int m = r0 + half * 8;
                float v0 = acc[mt][nt][half * 2 + 0] + b0;
                float v1 = acc[mt][nt][half * 2 + 1] + b1;
                if (!split) {
                    Y[(size_t)m * DMODEL + c0]     = v0;
                    Y[(size_t)m * DMODEL + c0 + 1] = v1;
                } else {
                    int b_ = m >> 11;
                    int s  = m & (SEQ - 1);
                    int h  = c0 >> 6;
                    int dh = c0 & (DHEAD - 1);
                    size_t base = (((size_t)(b_ * NHEADS + h)) * SEQ + s) * DHEAD;
                    Y[base + dh]     = v0;
                    Y[base + dh + 1] = v1;
                }
            }
        }
    }
}

// ---------------- attention: register flash + cp.async double buffer ------
// 256 threads = 8 warps; warp owns 16 q-rows x 64 key cols. Br=128/CTA.
// Smem float offsets: K0=0 (pitch 68), V0=4352 (pitch 72), K1=8960, V1=13312.
// Q staging [128][68] aliases buf0 region (8704 < 8960 floats).
#define KP 68
#define VP 72
#define A_K0 0
#define A_V0 4352
#define A_K1 8960
#define A_V1 13312
#define A_SMEM_FLOATS 17920    // 71680 bytes

__global__ __launch_bounds__(256) void attn_kernel(
    const float* __restrict__ Q, const float* __restrict__ K,
    const float* __restrict__ V, float* __restrict__ O)
{
    extern __shared__ float sm[];
    const uint32_t smb = smem_u32(sm);

    const int t    = threadIdx.x;
    const int lane = t & 31;
    const int wid  = t >> 5;
    const int gid  = lane >> 2;
    const int tg   = lane & 3;

    const int b  = blockIdx.z, h = blockIdx.y;
    const int q0 = blockIdx.x << 7;
    const size_t head_base = ((size_t)(b * NHEADS + h)) * SEQ * DHEAD;

    // ---- stage Q (scaled 1/8, tf32) into smem [128][68], extract frags ----
    {
        float (*Qs)[KP] = (float (*)[KP])sm;
        #pragma unroll
        for (int l = 0; l < 8; l++) {
            int id = t + 256 * l;
            int r  = id >> 4;
            int d4 = (id & 15) << 2;
            float4 v = *(const float4*)&Q[head_base + (size_t)(q0 + r) * DHEAD + d4];
            Qs[r][d4+0] = cvt_tf32f(v.x * 0.125f);
            Qs[r][d4+1] = cvt_tf32f(v.y * 0.125f);
            Qs[r][d4+2] = cvt_tf32f(v.z * 0.125f);
            Qs[r][d4+3] = cvt_tf32f(v.w * 0.125f);
        }
    }
    __syncthreads();

    unsigned qf[8][4];
    {
        float (*Qs)[KP] = (float (*)[KP])sm;
        const int wrow = wid * 16;
        #pragma unroll
        for (int ks = 0; ks < 8; ks++) {
            const int kb = ks * 8;
            qf[ks][0] = __float_as_uint(Qs[wrow + gid    ][kb + tg    ]);
            qf[ks][1] = __float_as_uint(Qs[wrow + gid + 8][kb + tg    ]);
            qf[ks][2] = __float_as_uint(Qs[wrow + gid    ][kb + 4 + tg]);
            qf[ks][3] = __float_as_uint(Qs[wrow + gid + 8][kb + 4 + tg]);
        }
    }
    __syncthreads();   // Q reads done before buf0 prefetch overwrites staging

    // ---- prefetch KV tile 0 into buf0 ----
    {
        #pragma unroll
        for (int l = 0; l < 4; l++) {
            int id = t + 256 * l;
            int r  = id >> 4;
            int c4 = (id & 15) << 2;
            cpa16(smb + (uint32_t)(A_K0 + r * KP + c4) * 4,
                  K + head_base + (size_t)r * DHEAD + c4);
            cpa16(smb + (uint32_t)(A_V0 + r * VP + c4) * 4,
                  V + head_base + (size_t)r * DHEAD + c4);
        }
        CPA_COMMIT();
    }

    float oacc[8][4];
    #pragma unroll
    for (int nt = 0; nt < 8; nt++)
        #pragma unroll
        for (int i = 0; i < 4; i++) oacc[nt][i] = 0.f;
    float m0 = -1e30f, m1 = -1e30f, l0 = 0.f, l1 = 0.f;

    const int src1 = (lane & ~3) | (tg >> 1);
    const int src2 = src1 + 2;
    const bool odd = (tg & 1);

    for (int it = 0; it < SEQ / 64; it++) {
        const int koff = (it & 1) ? A_K1 : A_K0;
        const int voff = (it & 1) ? A_V1 : A_V0;

        if (it + 1 < SEQ / 64) {
            const int nk = ((it + 1) & 1) ? A_K1 : A_K0;
            const int nv = ((it + 1) & 1) ? A_V1 : A_V0;
            const size_t gofs = head_base + (size_t)(it + 1) * 64 * DHEAD;
            #pragma unroll
            for (int l = 0; l < 4; l++) {
                int id = t + 256 * l;
                int r  = id >> 4;
                int c4 = (id & 15) << 2;
                cpa16(smb + (uint32_t)(nk + r * KP + c4) * 4,
                      K + gofs + (size_t)r * DHEAD + c4);
                cpa16(smb + (uint32_t)(nv + r * VP + c4) * 4,
                      V + gofs + (size_t)r * DHEAD + c4);
            }
            CPA_COMMIT();
            CPA_WAIT1();
        } else {
            CPA_WAIT0();
        }
        __syncthreads();

        // ---- in-place RNA tf32 conversion of this buffer ----
        #pragma unroll
        for (int l = 0; l < 4; l++) {
            int id = t + 256 * l;
            int r  = id >> 4;
            int c4 = (id & 15) << 2;
            float4* pk = (float4*)&sm[koff + r * KP + c4];
            float4 k4 = *pk;
            k4.x = cvt_tf32f(k4.x); k4.y = cvt_tf32f(k4.y);
            k4.z = cvt_tf32f(k4.z); k4.w = cvt_tf32f(k4.w);
            *pk = k4;
            float4* pv = (float4*)&sm[voff + r * VP + c4];
            float4 v4 = *pv;
            v4.x = cvt_tf32f(v4.x); v4.y = cvt_tf32f(v4.y);
            v4.z = cvt_tf32f(v4.z); v4.w = cvt_tf32f(v4.w);
            *pv = v4;
        }
        __syncthreads();

        const float* Ks = sm + koff;
        const float* Vs = sm + voff;

        // ---- S = (Q/8) K^T ----
        float sacc[8][4];
        #pragma unroll
        for (int nt = 0; nt < 8; nt++)
            #pragma unroll
            for (int i = 0; i < 4; i++) sacc[nt][i] = 0.f;

        #pragma unroll
        for (int ks = 0; ks < 8; ks++) {
            const int kb = ks * 8;
            unsigned bfr[8][2];
            #pragma unroll
            for (int nt = 0; nt < 8; nt++) {
                bfr[nt][0] = __float_as_uint(Ks[(nt * 8 + gid) * KP + kb + tg    ]);
                bfr[nt][1] = __float_as_uint(Ks[(nt * 8 + gid) * KP + kb + 4 + tg]);
            }
            #pragma unroll
            for (int nt = 0; nt < 8; nt++)
                mma_tf32(sacc[nt], qf[ks], bfr[nt]);
        }

        // ---- online softmax (regs + quad shuffles) ----
        float mx0 = -1e30f, mx1 = -1e30f;
        #pragma unroll
        for (int nt = 0; nt < 8; nt++) {
            mx0 = fmaxf(mx0, fmaxf(sacc[nt][0], sacc[nt][1]));
            mx1 = fmaxf(mx1, fmaxf(sacc[nt][2], sacc[nt][3]));
        }
        mx0 = fmaxf(mx0, __shfl_xor_sync(0xffffffffu, mx0, 1));
        mx0 = fmaxf(mx0, __shfl_xor_sync(0xffffffffu, mx0, 2));
        mx1 = fmaxf(mx1, __shfl_xor_sync(0xffffffffu, mx1, 1));
        mx1 = fmaxf(mx1, __shfl_xor_sync(0xffffffffu, mx1, 2));

        float m0n = fmaxf(m0, mx0), m1n = fmaxf(m1, mx1);
        float sc0 = __expf(m0 - m0n), sc1 = __expf(m1 - m1n);
        m0 = m0n; m1 = m1n;

        float s0 = 0.f, s1 = 0.f;
        #pragma unroll
        for (int nt = 0; nt < 8; nt++) {
            sacc[nt][0] = __expf(sacc[nt][0] - m0); s0 += sacc[nt][0];
            sacc[nt][1] = __expf(sacc[nt][1] - m0); s0 += sacc[nt][1];
            sacc[nt][2] = __expf(sacc[nt][2] - m1); s1 += sacc[nt][2];
            sacc[nt][3] = __expf(sacc[nt][3] - m1); s1 += sacc[nt][3];
        }
        s0 += __shfl_xor_sync(0xffffffffu, s0, 1);
        s0 += __shfl_xor_sync(0xffffffffu, s0, 2);
        s1 += __shfl_xor_sync(0xffffffffu, s1, 1);
        s1 += __shfl_xor_sync(0xffffffffu, s1, 2);
        l0 = l0 * sc0 + s0;
        l1 = l1 * sc1 + s1;

        #pragma unroll
        for (int nt = 0; nt < 8; nt++) {
            oacc[nt][0] *= sc0; oacc[nt][1] *= sc0;
            oacc[nt][2] *= sc1; oacc[nt][3] *= sc1;
        }

        // ---- PV ----
        #pragma unroll
        for (int ks = 0; ks < 8; ks++) {
            float p0 = sacc[ks][0], p1 = sacc[ks][1];
            float p2 = sacc[ks][2], p3 = sacc[ks][3];
            float v00 = __shfl_sync(0xffffffffu, p0, src1);
            float v01 = __shfl_sync(0xffffffffu, p1, src1);
            float v10 = __shfl_sync(0xffffffffu, p2, src1);
            float v11 = __shfl_sync(0xffffffffu, p3, src1);
            float v20 = __shfl_sync(0xffffffffu, p0, src2);
            float v21 = __shfl_sync(0xffffffffu, p1, src2);
            float v30 = __shfl_sync(0xffffffffu, p2, src2);
            float v31 = __shfl_sync(0xffffffffu, p3, src2);
            unsigned a[4];
            a[0] = f2tf32(odd ? v01 : v00);
            a[1] = f2tf32(odd ? v11 : v10);
            a[2] = f2tf32(odd ? v21 : v20);
            a[3] = f2tf32(odd ? v31 : v30);

            const int kb = ks * 8;
            #pragma unroll
            for (int nt = 0; nt < 8; nt++) {
                unsigned b2[2];
                b2[0] = __float_as_uint(Vs[(kb + tg    ) * VP + nt * 8 + gid]);
                b2[1] = __float_as_uint(Vs[(kb + 4 + tg) * VP + nt * 8 + gid]);
                mma_tf32(oacc[nt], a, b2);
            }
        }
        __syncthreads();   // before next iter's prefetch overwrites this buf
    }

    // ---- epilogue: normalize, write [B,S,D] (concat heads) ----
    {
        float il0 = 1.0f / l0, il1 = 1.0f / l1;
        int r0 = q0 + wid * 16 + gid;
        int r1 = r0 + 8;
        #pragma unroll
        for (int nt = 0; nt < 8; nt++) {
            int c = h * DHEAD + nt * 8 + tg * 2;
            float2 o0 = make_float2(oacc[nt][0] * il0, oacc[nt][1] * il0);
            float2 o1 = make_float2(oacc[nt][2] * il1, oacc[nt][3] * il1);
            *(float2*)&O[((size_t)(b * SEQ + r0)) * DMODEL + c] = o0;
            *(float2*)&O[((size_t)(b * SEQ + r1)) * DMODEL + c] = o1;
        }
    }
}

extern "C" void kernel_launch(void* const* d_in, const int* in_sizes, int n_in,
                              void* d_out, int out_size)
{
    const float* query = (const float*)d_in[0];
    const float* key_  = (const float*)d_in[1];
    const float* value = (const float*)d_in[2];
    const float* Wq = (const float*)d_in[3];
    const float* bq = (const float*)d_in[4];
    const float* Wk = (const float*)d_in[5];
    const float* bk = (const float*)d_in[6];
    const float* Wv = (const float*)d_in[7];
    const float* bv = (const float*)d_in[8];
    const float* Wo = (const float*)d_in[9];
    const float* bo = (const float*)d_in[10];

    float *qptr, *kptr, *vptr, *aoptr;
    cudaGetSymbolAddress((void**)&qptr,  g_q);
    cudaGetSymbolAddress((void**)&kptr,  g_k);
    cudaGetSymbolAddress((void**)&vptr,  g_v);
    cudaGetSymbolAddress((void**)&aoptr, g_ao);

    const int gemm_smem = G_SMEM_FLOATS * sizeof(float);   // 73728
    const int attn_smem = A_SMEM_FLOATS * sizeof(float);   // 71680
    cudaFuncSetAttribute(gemm_tf32, cudaFuncAttributeMaxDynamicSharedMemorySize, gemm_smem);
    cudaFuncSetAttribute(attn_kernel, cudaFuncAttributeMaxDynamicSharedMemorySize, attn_smem);

    dim3 ggrid(DMODEL / 128, MROWS / 128);   // (8, 32)
    gemm_tf32<<<ggrid, 256, gemm_smem>>>(query, Wq, bq, qptr, 1);
    gemm_tf32<<<ggrid, 256, gemm_smem>>>(key_,  Wk, bk, kptr, 1);
    gemm_tf32<<<ggrid, 256, gemm_smem>>>(value, Wv, bv, vptr, 1);

    dim3 agrid(SEQ / 128, NHEADS, BATCH);    // (16, 16, 2)
    attn_kernel<<<agrid, 256, attn_smem>>>(qptr, kptr, vptr, aoptr);

    gemm_tf32<<<ggrid, 256, gemm_smem>>>(aoptr, Wo, bo, (float*)d_out, 0);
}